// round 14
// baseline (speedup 1.0000x reference)
#include <cuda_runtime.h>
#include <cuda_fp16.h>
#include <cstdint>

#define BB 2
#define SS 2048
#define EE 1024
#define HH 16
#define DD 64
#define QKPLANE (BB * HH * SS * DD)

__device__ __half g_x16[4096 * 1024];
__device__ __half g_wq16[3072 * 1024];
__device__ __half g_wo16[1024 * 1024];
__device__ __half g_q16[QKPLANE];                 // [b][h][s][d]
__device__ __half g_k16[QKPLANE];
__device__ __half g_vt16[QKPLANE];                // [b][h][d][k]
__device__ __half g_ctx16[BB * SS * EE];          // [b][s][h*64+d]

// ===========================================================================
// helpers
// ===========================================================================
__device__ __forceinline__ uint32_t smem_u32(const void* p) {
    uint32_t a;
    asm("{ .reg .u64 t; cvta.to.shared.u64 t, %1; cvt.u32.u64 %0, t; }"
        : "=r"(a) : "l"(p));
    return a;
}
__device__ __forceinline__ void cp_async16(uint32_t saddr, const void* g) {
    asm volatile("cp.async.cg.shared.global [%0], [%1], 16;\n" :: "r"(saddr), "l"(g));
}
__device__ __forceinline__ void cp_commit() {
    asm volatile("cp.async.commit_group;\n" ::: "memory");
}
__device__ __forceinline__ void ldsm4(uint32_t& r0, uint32_t& r1, uint32_t& r2,
                                      uint32_t& r3, uint32_t a) {
    asm volatile("ldmatrix.sync.aligned.m8n8.x4.shared.b16 {%0,%1,%2,%3}, [%4];"
                 : "=r"(r0), "=r"(r1), "=r"(r2), "=r"(r3) : "r"(a));
}
__device__ __forceinline__ void mma_f16(float* c, const uint32_t* a, uint32_t b0,
                                        uint32_t b1) {
    asm volatile(
        "mma.sync.aligned.m16n8k16.row.col.f32.f16.f16.f32 "
        "{%0,%1,%2,%3},{%4,%5,%6,%7},{%8,%9},{%0,%1,%2,%3};"
        : "+f"(c[0]), "+f"(c[1]), "+f"(c[2]), "+f"(c[3])
        : "r"(a[0]), "r"(a[1]), "r"(a[2]), "r"(a[3]), "r"(b0), "r"(b1));
}
__device__ __forceinline__ uint32_t pack_h2(float a, float b) {
    uint32_t r;
    asm("cvt.rn.f16x2.f32 %0, %1, %2;" : "=r"(r) : "f"(b), "f"(a));
    return r;
}

// ===========================================================================
// fp32 -> fp16 convert
// ===========================================================================
__global__ __launch_bounds__(256) void cvt16(const float4* __restrict__ src,
                                             uint2* __restrict__ dst) {
    int i = blockIdx.x * 256 + threadIdx.x;
    float4 v = src[i];
    dst[i] = make_uint2(pack_h2(v.x, v.y), pack_h2(v.z, v.w));
}

// ===========================================================================
// fp16 HMMA NT GEMM (projections only) — unchanged from R12 (passing).
// MODE 0: out-proj (bias, fp32 out N=1024)
// MODE 1: QKV (bias; Q,K fp16 [b][h][s][d]; V fp16 transposed [b][h][d][k])
// ===========================================================================
template <int MODE, int NT, int K, int KB>
__global__ __launch_bounds__(256, 2) void tgemm16(
    const __half* __restrict__ A0, const __half* __restrict__ W0,
    const float* __restrict__ bias, float* __restrict__ Cout) {
    extern __shared__ char dsm[];
    uint32_t sbase = smem_u32(dsm);
    constexpr int PITCH = KB * 2 + 16;
    constexpr int TILE_A = 128 * PITCH;
    constexpr int TILE_W = NT * PITCH;
    constexpr int BUF = TILE_A + TILE_W;
    constexpr int NP = NT / 32;
    constexpr int SEG = KB / 8;
    constexpr int NKS = KB / 16;

    const __half* A = A0;
    const __half* W = W0;

    int tid = threadIdx.x, lane = tid & 31, wid = tid >> 5;
    int wm = wid & 3, wn = wid >> 2;
    int m0 = blockIdx.y * 128, n0 = blockIdx.x * NT;

    float acc[2][2 * NP][4];
#pragma unroll
    for (int i = 0; i < 2; i++)
#pragma unroll
        for (int j = 0; j < 2 * NP; j++)
#pragma unroll
            for (int q = 0; q < 4; q++) acc[i][j][q] = 0.f;

    const int NC = K / KB;

    auto issue = [&](int c) {
        uint32_t sb = sbase + (c & 1) * BUF;
        int gc = c * KB;
#pragma unroll
        for (int it = 0; it < 128 * SEG / 256; it++) {
            int idx = tid + it * 256;
            int row = idx / SEG, seg = idx % SEG;
            cp_async16(sb + (uint32_t)(row * PITCH + seg * 16),
                       A + (size_t)(m0 + row) * K + gc + seg * 8);
        }
#pragma unroll
        for (int it = 0; it < NT * SEG / 256; it++) {
            int idx = tid + it * 256;
            int row = idx / SEG, seg = idx % SEG;
            cp_async16(sb + (uint32_t)(TILE_A + row * PITCH + seg * 16),
                       W + (size_t)(n0 + row) * K + gc + seg * 8);
        }
        cp_commit();
    };

    issue(0);

    for (int c = 0; c < NC; c++) {
        if (c + 1 < NC) {
            issue(c + 1);
            asm volatile("cp.async.wait_group 1;\n" ::: "memory");
        } else {
            asm volatile("cp.async.wait_group 0;\n" ::: "memory");
        }
        __syncthreads();

        uint32_t sb = sbase + (c & 1) * BUF;
        uint32_t a_addr = sb + (uint32_t)((wm * 32 + (lane & 15)) * PITCH + (lane >> 4) * 16);
        uint32_t b_addr = sb + TILE_A +
                          (uint32_t)((wn * (NT / 2) + (lane >> 4) * 8 + (lane & 7)) * PITCH +
                                     ((lane >> 3) & 1) * 16);

#pragma unroll
        for (int ks = 0; ks < NKS; ks++) {
            uint32_t ah[2][4];
#pragma unroll
            for (int mb = 0; mb < 2; mb++) {
                uint32_t ao = a_addr + ks * 32 + mb * (16 * PITCH);
                ldsm4(ah[mb][0], ah[mb][1], ah[mb][2], ah[mb][3], ao);
            }
#pragma unroll
            for (int np = 0; np < NP; np++) {
                uint32_t bo = b_addr + ks * 32 + np * (16 * PITCH);
                uint32_t h0, h1, h2, h3;
                ldsm4(h0, h1, h2, h3, bo);
#pragma unroll
                for (int mb = 0; mb < 2; mb++) {
                    mma_f16(acc[mb][2 * np],     ah[mb], h0, h1);
                    mma_f16(acc[mb][2 * np + 1], ah[mb], h2, h3);
                }
            }
        }
        __syncthreads();
    }

    int lr = lane >> 2, lc = lane & 3;
#pragma unroll
    for (int mb = 0; mb < 2; mb++) {
#pragma unroll
        for (int nb = 0; nb < 2 * NP; nb++) {
            int n = n0 + wn * (NT / 2) + nb * 8 + lc * 2;
            int m_lo = m0 + wm * 32 + mb * 16 + lr;
            float* a4 = acc[mb][nb];
            if constexpr (MODE == 0) {
                float2 bv = *(const float2*)(bias + n);
                *(float2*)(Cout + (size_t)m_lo * 1024 + n) =
                    make_float2(a4[0] + bv.x, a4[1] + bv.y);
                *(float2*)(Cout + (size_t)(m_lo + 8) * 1024 + n) =
                    make_float2(a4[2] + bv.x, a4[3] + bv.y);
            } else {
                float2 bv = *(const float2*)(bias + n);
                int which = n >> 10;
                int hh = (n & 1023) >> 6;
                int d = n & 63;
#pragma unroll
                for (int half_ = 0; half_ < 2; half_++) {
                    int m = m_lo + half_ * 8;
                    int b_ = m >> 11;
                    int s = m & 2047;
                    float v0 = a4[2 * half_] + bv.x;
                    float v1 = a4[2 * half_ + 1] + bv.y;
                    if (which == 2) {
                        size_t tb = ((size_t)(b_ * HH + hh) * DD + d) * SS + s;
                        g_vt16[tb] = __float2half_rn(v0);
                        g_vt16[tb + SS] = __float2half_rn(v1);
                    } else {
                        size_t idx = (((size_t)b_ * HH + hh) * SS + s) * DD + d;
                        uint32_t* ph = which ? (uint32_t*)g_k16 : (uint32_t*)g_q16;
                        ph[idx >> 1] = pack_h2(v0, v1);
                    }
                }
            }
        }
    }
}

// ===========================================================================
// Fused attention v2: scores + softmax-over-heads + PV, one kernel.
// Grid = (b, 32-query tile) = 128 CTAs, 1024 threads (32 warps).
// Warp w: h = w>>1, half = w&1 (q-half in S phase, d-half in PV phase).
// Q held in registers (staged once through the K-buffer smem region).
// K tiles: [h][k(16)][d(64)] pitch 144, x2 buffers.
// Vt tiles: [h][d(64)][k(16)] pitch 48, x2 buffers.
// P exchange: [h][q(32)][k(16)] fp16, pitch 48.
// All pitches are multiples of 16B (cp.async/ldmatrix alignment).
// ===========================================================================
#define TQA 32
#define KT 16
#define KSZ 36864                 // 16h * 16k * 144
#define VSZ 49152                 // 16h * 64d * 48
#define VS_OFF (2 * KSZ)          // 73728
#define EP_OFF (VS_OFF + 2 * VSZ) // 172032
#define ATT_SMEM (EP_OFF + 16 * 32 * 48)   // 196608

__global__ __launch_bounds__(1024, 1) void fused_attn() {
    extern __shared__ char sm[];
    uint32_t sb = smem_u32(sm);
    int tid = threadIdx.x, lane = tid & 31, wid = tid >> 5;
    int h = wid >> 1, half = wid & 1;
    int b = blockIdx.x >> 6;
    int q0 = (blockIdx.x & 63) * TQA;

    const __half* Qg = g_q16 + (size_t)b * HH * SS * DD;
    const __half* Kg = g_k16 + (size_t)b * HH * SS * DD;
    const __half* Vtg = g_vt16 + (size_t)b * HH * DD * SS;

    // ---- stage Q [16h][32q][64d] pitch 144 into K-buffer region, then to regs
#pragma unroll
    for (int it = 0; it < 4; it++) {
        int idx = tid + it * 1024;
        int r = idx >> 3, seg = idx & 7;            // r = h*32 + q
        cp_async16(sb + (uint32_t)(r * 144 + seg * 16),
                   Qg + ((size_t)(r >> 5) * SS + q0 + (r & 31)) * DD + seg * 8);
    }
    cp_commit();
    asm volatile("cp.async.wait_group 0;\n" ::: "memory");
    __syncthreads();

    uint32_t qf[4][4];
    {
        uint32_t qa = sb + (uint32_t)((h * 32 + half * 16 + (lane & 15)) * 144 +
                                      (lane >> 4) * 16);
#pragma unroll
        for (int ks = 0; ks < 4; ks++)
            ldsm4(qf[ks][0], qf[ks][1], qf[ks][2], qf[ks][3], qa + ks * 32);
    }
    __syncthreads();   // all warps done reading Q before K overwrites region

    auto issueKV = [&](int c) {
        int k0 = c * KT;
        uint32_t kb = sb + (c & 1) * KSZ;
        uint32_t vb = sb + VS_OFF + (c & 1) * VSZ;
#pragma unroll
        for (int it = 0; it < 2; it++) {
            int idx = tid + it * 1024;
            int r = idx >> 3, seg = idx & 7;        // r = h*16 + k
            cp_async16(kb + (uint32_t)(r * 144 + seg * 16),
                       Kg + ((size_t)(r >> 4) * SS + k0 + (r & 15)) * DD + seg * 8);
        }
#pragma unroll
        for (int it = 0; it < 2; it++) {
            int idx = tid + it * 1024;
            int r = idx >> 1, seg = idx & 1;        // r = h*64 + d
            cp_async16(vb + (uint32_t)(r * 48 + seg * 16),
                       Vtg + (size_t)r * SS + k0 + seg * 8);
        }
        cp_commit();
    };

    issueKV(0);

    float ctx[2][4][4];
#pragma unroll
    for (int i = 0; i < 2; i++)
#pragma unroll
        for (int j = 0; j < 4; j++)
#pragma unroll
            for (int q = 0; q < 4; q++) ctx[i][j][q] = 0.f;

    const int NC = SS / KT;   // 128
    int lr = lane >> 2, lc = lane & 3;

    for (int c = 0; c < NC; c++) {
        if (c + 1 < NC) {
            issueKV(c + 1);
            asm volatile("cp.async.wait_group 1;\n" ::: "memory");
        } else {
            asm volatile("cp.async.wait_group 0;\n" ::: "memory");
        }
        __syncthreads();

        uint32_t kb = sb + (c & 1) * KSZ;
        uint32_t vb = sb + VS_OFF + (c & 1) * VSZ;

        // ---- S = Q K^T (m16q x n16k x k64d) ----
        float sacc[2][4];
#pragma unroll
        for (int j = 0; j < 2; j++)
#pragma unroll
            for (int q = 0; q < 4; q++) sacc[j][q] = 0.f;

        uint32_t ka = kb + (uint32_t)((h * 16 + (lane >> 4) * 8 + (lane & 7)) * 144 +
                                      ((lane >> 3) & 1) * 16);
#pragma unroll
        for (int ks = 0; ks < 4; ks++) {
            uint32_t b0, b1, b2, b3;
            ldsm4(b0, b1, b2, b3, ka + ks * 32);
            mma_f16(sacc[0], qf[ks], b0, b1);
            mma_f16(sacc[1], qf[ks], b2, b3);
        }

        // ---- e = exp(S/32) -> P exchange [h][q][k] pitch 48 ----
        {
            int q = half * 16 + lr;
            uint32_t ep = sb + EP_OFF + (uint32_t)(h * 1536 + q * 48);
#pragma unroll
            for (int nb = 0; nb < 2; nb++) {
                int k = nb * 8 + lc * 2;
                uint32_t p01 = pack_h2(__expf(sacc[nb][0] * 0.03125f),
                                       __expf(sacc[nb][1] * 0.03125f));
                uint32_t p23 = pack_h2(__expf(sacc[nb][2] * 0.03125f),
                                       __expf(sacc[nb][3] * 0.03125f));
                asm volatile("st.shared.u32 [%0], %1;" :: "r"(ep + k * 2), "r"(p01));
                asm volatile("st.shared.u32 [%0], %1;" :: "r"(ep + 8 * 48 + k * 2), "r"(p23));
            }
        }
        __syncthreads();

        // ---- softmax over heads: 512 threads own (q,k) ----
        if (tid < 512) {
            int q = tid >> 4, k = tid & 15;
            char* base = sm + EP_OFF + q * 48 + k * 2;
            float ev[16];
            float s = 0.f;
#pragma unroll
            for (int hh = 0; hh < 16; hh++) {
                ev[hh] = __half2float(*(__half*)(base + hh * 1536));
                s += ev[hh];
            }
            float r = __fdividef(1.f, s);
#pragma unroll
            for (int hh = 0; hh < 16; hh++)
                *(__half*)(base + hh * 1536) = __float2half_rn(ev[hh] * r);
        }
        __syncthreads();

        // ---- PV: ctx (m32q x n32d-half x k16) ----
        uint32_t pa = sb + EP_OFF + (uint32_t)(h * 1536 + (lane & 15) * 48 +
                                               (lane >> 4) * 16);
        uint32_t va = vb + (uint32_t)((h * 64 + half * 32 + (lane >> 4) * 8 +
                                       (lane & 7)) * 48 + ((lane >> 3) & 1) * 16);
        uint32_t pf[2][4];
#pragma unroll
        for (int mb = 0; mb < 2; mb++)
            ldsm4(pf[mb][0], pf[mb][1], pf[mb][2], pf[mb][3], pa + mb * (16 * 48));
#pragma unroll
        for (int np = 0; np < 2; np++) {
            uint32_t b0, b1, b2, b3;
            ldsm4(b0, b1, b2, b3, va + np * (16 * 48));
#pragma unroll
            for (int mb = 0; mb < 2; mb++) {
                mma_f16(ctx[mb][2 * np],     pf[mb], b0, b1);
                mma_f16(ctx[mb][2 * np + 1], pf[mb], b2, b3);
            }
        }
        __syncthreads();
    }

    // ---- epilogue: ctx -> g_ctx16 [b][s][h*64+d] fp16 ----
    uint32_t* ch = (uint32_t*)g_ctx16;
#pragma unroll
    for (int mb = 0; mb < 2; mb++) {
#pragma unroll
        for (int nb = 0; nb < 4; nb++) {
            int q = mb * 16 + lr;
            int d = half * 32 + nb * 8 + lc * 2;
            float* a4 = ctx[mb][nb];
            size_t i0 = ((size_t)(b * SS + q0 + q) * EE + h * DD + d) >> 1;
            ch[i0] = pack_h2(a4[0], a4[1]);
            ch[i0 + 4 * EE] = pack_h2(a4[2], a4[3]);
        }
    }
}

// ===========================================================================
extern "C" void kernel_launch(void* const* d_in, const int* in_sizes, int n_in,
                              void* d_out, int out_size) {
    const float* x     = (const float*)d_in[0];
    const float* w_qkv = (const float*)d_in[1];
    const float* b_qkv = (const float*)d_in[2];
    const float* w_out = (const float*)d_in[3];
    const float* b_out = (const float*)d_in[4];
    float* out = (float*)d_out;

    void *p_x, *p_wq, *p_wo, *p_ctx;
    cudaGetSymbolAddress(&p_x, g_x16);
    cudaGetSymbolAddress(&p_wq, g_wq16);
    cudaGetSymbolAddress(&p_wo, g_wo16);
    cudaGetSymbolAddress(&p_ctx, g_ctx16);

    const int SM_P = 2 * (128 * 144 + 128 * 144);   // 73728
    cudaFuncSetAttribute(tgemm16<1, 128, 1024, 64>, cudaFuncAttributeMaxDynamicSharedMemorySize, SM_P);
    cudaFuncSetAttribute(tgemm16<0, 128, 1024, 64>, cudaFuncAttributeMaxDynamicSharedMemorySize, SM_P);
    cudaFuncSetAttribute(fused_attn, cudaFuncAttributeMaxDynamicSharedMemorySize, ATT_SMEM);

    // 1) fp32 -> fp16 converts
    cvt16<<<4096, 256>>>((const float4*)x, (uint2*)p_x);
    cvt16<<<3072, 256>>>((const float4*)w_qkv, (uint2*)p_wq);
    cvt16<<<1024, 256>>>((const float4*)w_out, (uint2*)p_wo);

    // 2) QKV projection -> Q,K fp16 + V fp16 transposed
    tgemm16<1, 128, 1024, 64><<<dim3(24, 32, 1), 256, SM_P>>>(
        (const __half*)p_x, (const __half*)p_wq, b_qkv, nullptr);

    // 3) fused attention -> ctx fp16
    fused_attn<<<BB * (SS / TQA), 1024, ATT_SMEM>>>();

    // 4) out-projection -> fp32 out
    tgemm16<0, 128, 1024, 64><<<dim3(8, 32, 1), 256, SM_P>>>(
        (const __half*)p_ctx, (const __half*)p_wo, b_out, out);
}

// round 15
// speedup vs baseline: 1.3081x; 1.3081x over previous
#include <cuda_runtime.h>
#include <cuda_fp16.h>
#include <cstdint>

#define BB 2
#define SS 2048
#define EE 1024
#define HH 16
#define DD 64
#define QKPLANE (BB * HH * SS * DD)
#define SPLANE ((size_t)SS * SS)

__device__ __half g_x16[4096 * 1024];
__device__ __half g_wq16[3072 * 1024];
__device__ __half g_wo16[1024 * 1024];
__device__ __half g_q16[QKPLANE];                 // [b][h][s][d]
__device__ __half g_k16[QKPLANE];
__device__ __half g_vt16[QKPLANE];                // [b][h][d][k]
__device__ __half g_S16[(size_t)BB * HH * SS * SS];
__device__ __half g_P16[(size_t)BB * HH * SS * SS];
__device__ __half g_ctx16[BB * SS * EE];          // [b][s][h*64+d]

// ===========================================================================
// helpers
// ===========================================================================
__device__ __forceinline__ uint32_t smem_u32(const void* p) {
    uint32_t a;
    asm("{ .reg .u64 t; cvta.to.shared.u64 t, %1; cvt.u32.u64 %0, t; }"
        : "=r"(a) : "l"(p));
    return a;
}
__device__ __forceinline__ void cp_async16(uint32_t saddr, const void* g) {
    asm volatile("cp.async.cg.shared.global [%0], [%1], 16;\n" :: "r"(saddr), "l"(g));
}
__device__ __forceinline__ void cp_commit() {
    asm volatile("cp.async.commit_group;\n" ::: "memory");
}
__device__ __forceinline__ void ldsm4(uint32_t& r0, uint32_t& r1, uint32_t& r2,
                                      uint32_t& r3, uint32_t a) {
    asm volatile("ldmatrix.sync.aligned.m8n8.x4.shared.b16 {%0,%1,%2,%3}, [%4];"
                 : "=r"(r0), "=r"(r1), "=r"(r2), "=r"(r3) : "r"(a));
}
__device__ __forceinline__ void mma_f16(float* c, const uint32_t* a, uint32_t b0,
                                        uint32_t b1) {
    asm volatile(
        "mma.sync.aligned.m16n8k16.row.col.f32.f16.f16.f32 "
        "{%0,%1,%2,%3},{%4,%5,%6,%7},{%8,%9},{%0,%1,%2,%3};"
        : "+f"(c[0]), "+f"(c[1]), "+f"(c[2]), "+f"(c[3])
        : "r"(a[0]), "r"(a[1]), "r"(a[2]), "r"(a[3]), "r"(b0), "r"(b1));
}
__device__ __forceinline__ uint32_t pack_h2(float a, float b) {
    uint32_t r;
    asm("cvt.rn.f16x2.f32 %0, %1, %2;" : "=r"(r) : "f"(b), "f"(a));
    return r;
}

// ===========================================================================
// fp32 -> fp16 convert
// ===========================================================================
__global__ __launch_bounds__(256) void cvt16(const float4* __restrict__ src,
                                             uint2* __restrict__ dst) {
    int i = blockIdx.x * 256 + threadIdx.x;
    float4 v = src[i];
    dst[i] = make_uint2(pack_h2(v.x, v.y), pack_h2(v.z, v.w));
}

// ===========================================================================
// softmax over HEAD axis (fp16 S -> fp16 P)
// ===========================================================================
__global__ __launch_bounds__(256) void softmax16() {
    int idx = blockIdx.x * 256 + threadIdx.x;
    int k4 = idx & 511;
    int q = (idx >> 9) & 2047;
    int b = idx >> 20;
    const uint2* Sp = (const uint2*)g_S16;
    uint2* Pp = (uint2*)g_P16;
    size_t base = ((size_t)(b * HH) * SS + q) * 512 + k4;
    size_t hstep = (size_t)SS * 512;

    float4 e[16];
    float4 ds = make_float4(0.f, 0.f, 0.f, 0.f);
#pragma unroll
    for (int h = 0; h < 16; h++) {
        uint2 u = Sp[base + (size_t)h * hstep];
        float2 f0 = __half22float2(*(const __half2*)&u.x);
        float2 f1 = __half22float2(*(const __half2*)&u.y);
        e[h].x = __expf(f0.x * 0.03125f);
        e[h].y = __expf(f0.y * 0.03125f);
        e[h].z = __expf(f1.x * 0.03125f);
        e[h].w = __expf(f1.y * 0.03125f);
        ds.x += e[h].x; ds.y += e[h].y; ds.z += e[h].z; ds.w += e[h].w;
    }
    float4 r;
    r.x = __fdividef(1.f, ds.x);
    r.y = __fdividef(1.f, ds.y);
    r.z = __fdividef(1.f, ds.z);
    r.w = __fdividef(1.f, ds.w);
#pragma unroll
    for (int h = 0; h < 16; h++) {
        uint2 o;
        o.x = pack_h2(e[h].x * r.x, e[h].y * r.y);
        o.y = pack_h2(e[h].z * r.z, e[h].w * r.w);
        Pp[base + (size_t)h * hstep] = o;
    }
}

// ===========================================================================
// fp16 HMMA NT GEMM — 64x64 warp tiles (2x2 warp grid, 128 threads).
// CTA tile 128 x NT, chunk depth KB, double-buffered smem.
// MODE 0: out-proj (bias, fp32 out N=1024)
// MODE 1: QKV (bias; Q,K fp16 [b][h][s][d]; V fp16 transposed [b][h][d][k])
// MODE 2: scores (z=(b,h), fp16 S out)
// MODE 3: PV (z=(b,h), NT=64; fp16 ctx out [b][s][e])
// ===========================================================================
template <int MODE, int NT, int K, int KB>
__global__ __launch_bounds__(128, 2) void tgemm16(
    const __half* __restrict__ A0, const __half* __restrict__ W0,
    const float* __restrict__ bias, float* __restrict__ Cout,
    int strideA, int strideW) {
    extern __shared__ char dsm[];
    uint32_t sbase = smem_u32(dsm);
    constexpr int PITCH = KB * 2 + 16;
    constexpr int TILE_A = 128 * PITCH;
    constexpr int TILE_W = NT * PITCH;
    constexpr int BUF = TILE_A + TILE_W;
    constexpr int NP = NT / 32;          // B n16-blocks per warp (width NT/2)
    constexpr int SEG = KB / 8;
    constexpr int NKS = KB / 16;

    int z = blockIdx.z;
    const __half* A = A0 + (size_t)z * strideA;
    const __half* W = W0 + (size_t)z * strideW;

    int tid = threadIdx.x, lane = tid & 31, wid = tid >> 5;
    int wm = wid & 1, wn = wid >> 1;     // 2x2 warp grid, warp tile 64 x NT/2
    int m0 = blockIdx.y * 128, n0 = blockIdx.x * NT;

    float acc[4][2 * NP][4];
#pragma unroll
    for (int i = 0; i < 4; i++)
#pragma unroll
        for (int j = 0; j < 2 * NP; j++)
#pragma unroll
            for (int q = 0; q < 4; q++) acc[i][j][q] = 0.f;

    const int NC = K / KB;

    auto issue = [&](int c) {
        uint32_t sb = sbase + (c & 1) * BUF;
        int gc = c * KB;
#pragma unroll
        for (int it = 0; it < SEG; it++) {
            int idx = tid + it * 128;
            int row = idx / SEG, seg = idx % SEG;
            cp_async16(sb + (uint32_t)(row * PITCH + seg * 16),
                       A + (size_t)(m0 + row) * K + gc + seg * 8);
        }
#pragma unroll
        for (int it = 0; it < NT * SEG / 128; it++) {
            int idx = tid + it * 128;
            int row = idx / SEG, seg = idx % SEG;
            cp_async16(sb + (uint32_t)(TILE_A + row * PITCH + seg * 16),
                       W + (size_t)(n0 + row) * K + gc + seg * 8);
        }
        cp_commit();
    };

    issue(0);

    for (int c = 0; c < NC; c++) {
        if (c + 1 < NC) {
            issue(c + 1);
            asm volatile("cp.async.wait_group 1;\n" ::: "memory");
        } else {
            asm volatile("cp.async.wait_group 0;\n" ::: "memory");
        }
        __syncthreads();

        uint32_t sb = sbase + (c & 1) * BUF;
        uint32_t a_addr = sb + (uint32_t)((wm * 64 + (lane & 15)) * PITCH + (lane >> 4) * 16);
        uint32_t b_addr = sb + TILE_A +
                          (uint32_t)((wn * (NT / 2) + (lane >> 4) * 8 + (lane & 7)) * PITCH +
                                     ((lane >> 3) & 1) * 16);

#pragma unroll
        for (int ks = 0; ks < NKS; ks++) {
            uint32_t ah[4][4];
#pragma unroll
            for (int mb = 0; mb < 4; mb++) {
                uint32_t ao = a_addr + ks * 32 + mb * (16 * PITCH);
                ldsm4(ah[mb][0], ah[mb][1], ah[mb][2], ah[mb][3], ao);
            }
#pragma unroll
            for (int np = 0; np < NP; np++) {
                uint32_t bo = b_addr + ks * 32 + np * (16 * PITCH);
                uint32_t h0, h1, h2, h3;
                ldsm4(h0, h1, h2, h3, bo);
#pragma unroll
                for (int mb = 0; mb < 4; mb++) {
                    mma_f16(acc[mb][2 * np],     ah[mb], h0, h1);
                    mma_f16(acc[mb][2 * np + 1], ah[mb], h2, h3);
                }
            }
        }
        __syncthreads();
    }

    int lr = lane >> 2, lc = lane & 3;
#pragma unroll
    for (int mb = 0; mb < 4; mb++) {
#pragma unroll
        for (int nb = 0; nb < 2 * NP; nb++) {
            int n = n0 + wn * (NT / 2) + nb * 8 + lc * 2;
            int m_lo = m0 + wm * 64 + mb * 16 + lr;
            float* a4 = acc[mb][nb];
            if constexpr (MODE == 0) {
                float2 bv = *(const float2*)(bias + n);
                *(float2*)(Cout + (size_t)m_lo * 1024 + n) =
                    make_float2(a4[0] + bv.x, a4[1] + bv.y);
                *(float2*)(Cout + (size_t)(m_lo + 8) * 1024 + n) =
                    make_float2(a4[2] + bv.x, a4[3] + bv.y);
            } else if constexpr (MODE == 1) {
                float2 bv = *(const float2*)(bias + n);
                int which = n >> 10;
                int hh = (n & 1023) >> 6;
                int d = n & 63;
#pragma unroll
                for (int half_ = 0; half_ < 2; half_++) {
                    int m = m_lo + half_ * 8;
                    int b_ = m >> 11;
                    int s = m & 2047;
                    float v0 = a4[2 * half_] + bv.x;
                    float v1 = a4[2 * half_ + 1] + bv.y;
                    if (which == 2) {
                        size_t tb = ((size_t)(b_ * HH + hh) * DD + d) * SS + s;
                        g_vt16[tb] = __float2half_rn(v0);
                        g_vt16[tb + SS] = __float2half_rn(v1);
                    } else {
                        size_t idx = (((size_t)b_ * HH + hh) * SS + s) * DD + d;
                        uint32_t* ph = which ? (uint32_t*)g_k16 : (uint32_t*)g_q16;
                        ph[idx >> 1] = pack_h2(v0, v1);
                    }
                }
            } else if constexpr (MODE == 2) {
                uint32_t* Sp = (uint32_t*)(g_S16 + (size_t)z * SPLANE);
                Sp[((size_t)m_lo * SS + n) >> 1] = pack_h2(a4[0], a4[1]);
                Sp[((size_t)(m_lo + 8) * SS + n) >> 1] = pack_h2(a4[2], a4[3]);
            } else {
                int b_ = z >> 4, h_ = z & 15;
                uint32_t* ch = (uint32_t*)g_ctx16;
                size_t i0 = ((size_t)(b_ * SS + m_lo) * EE + h_ * DD + n) >> 1;
                ch[i0] = pack_h2(a4[0], a4[1]);
                ch[i0 + 4 * EE] = pack_h2(a4[2], a4[3]);
            }
        }
    }
}

// ===========================================================================
extern "C" void kernel_launch(void* const* d_in, const int* in_sizes, int n_in,
                              void* d_out, int out_size) {
    const float* x     = (const float*)d_in[0];
    const float* w_qkv = (const float*)d_in[1];
    const float* b_qkv = (const float*)d_in[2];
    const float* w_out = (const float*)d_in[3];
    const float* b_out = (const float*)d_in[4];
    float* out = (float*)d_out;

    void *p_x, *p_wq, *p_wo, *p_q, *p_k, *p_vt, *p_P, *p_ctx;
    cudaGetSymbolAddress(&p_x, g_x16);
    cudaGetSymbolAddress(&p_wq, g_wq16);
    cudaGetSymbolAddress(&p_wo, g_wo16);
    cudaGetSymbolAddress(&p_q, g_q16);
    cudaGetSymbolAddress(&p_k, g_k16);
    cudaGetSymbolAddress(&p_vt, g_vt16);
    cudaGetSymbolAddress(&p_P, g_P16);
    cudaGetSymbolAddress(&p_ctx, g_ctx16);

    const int SM_QKV = 2 * (128 * 144 + 128 * 144);   // 73728 (KB=64, NT=128)
    const int SM_SC  = 2 * (128 * 80 + 128 * 80);     // 40960 (KB=32, NT=128)
    const int SM_PV  = 2 * (128 * 144 + 64 * 144);    // 55296 (KB=64, NT=64)
    cudaFuncSetAttribute(tgemm16<1, 128, 1024, 64>, cudaFuncAttributeMaxDynamicSharedMemorySize, SM_QKV);
    cudaFuncSetAttribute(tgemm16<0, 128, 1024, 64>, cudaFuncAttributeMaxDynamicSharedMemorySize, SM_QKV);
    cudaFuncSetAttribute(tgemm16<2, 128, 64, 32>,   cudaFuncAttributeMaxDynamicSharedMemorySize, SM_SC);
    cudaFuncSetAttribute(tgemm16<3, 64, 2048, 64>,  cudaFuncAttributeMaxDynamicSharedMemorySize, SM_PV);

    // 1) fp32 -> fp16 converts
    cvt16<<<4096, 256>>>((const float4*)x, (uint2*)p_x);
    cvt16<<<3072, 256>>>((const float4*)w_qkv, (uint2*)p_wq);
    cvt16<<<1024, 256>>>((const float4*)w_out, (uint2*)p_wo);

    // 2) QKV projection -> Q,K fp16 + V fp16 transposed
    tgemm16<1, 128, 1024, 64><<<dim3(24, 32, 1), 128, SM_QKV>>>(
        (const __half*)p_x, (const __half*)p_wq, b_qkv, nullptr, 0, 0);

    // 3) scores S = Q K^T -> fp16
    tgemm16<2, 128, 64, 32><<<dim3(16, 16, 32), 128, SM_SC>>>(
        (const __half*)p_q, (const __half*)p_k, nullptr, nullptr,
        SS * DD, SS * DD);

    // 4) softmax over heads -> P fp16
    softmax16<<<8192, 256>>>();

    // 5) ctx = P V -> fp16 [b][s][e]
    tgemm16<3, 64, 2048, 64><<<dim3(1, 16, 32), 128, SM_PV>>>(
        (const __half*)p_P, (const __half*)p_vt, nullptr, nullptr,
        (int)SPLANE, DD * SS);

    // 6) out-projection -> fp32 out
    tgemm16<0, 128, 1024, 64><<<dim3(8, 32, 1), 128, SM_QKV>>>(
        (const __half*)p_ctx, (const __half*)p_wo, b_out, out, 0, 0);
}

// round 16
// speedup vs baseline: 1.4011x; 1.0711x over previous
#include <cuda_runtime.h>
#include <cuda_fp16.h>
#include <cstdint>

#define BB 2
#define SS 2048
#define EE 1024
#define HH 16
#define DD 64
#define QKPLANE (BB * HH * SS * DD)
#define SPLANE ((size_t)SS * SS)

__device__ __half g_x16[4096 * 1024];
__device__ __half g_wq16[3072 * 1024];
__device__ __half g_wo16[1024 * 1024];
__device__ __half g_q16[QKPLANE];                 // [b][h][s][d]
__device__ __half g_k16[QKPLANE];
__device__ __half g_vt16[QKPLANE];                // [b][h][d][k]
__device__ __half g_S16[(size_t)BB * HH * SS * SS];
__device__ __half g_P16[(size_t)BB * HH * SS * SS];
__device__ __half g_ctx16[BB * SS * EE];          // [b][s][h*64+d]

// ===========================================================================
// helpers
// ===========================================================================
__device__ __forceinline__ uint32_t smem_u32(const void* p) {
    uint32_t a;
    asm("{ .reg .u64 t; cvta.to.shared.u64 t, %1; cvt.u32.u64 %0, t; }"
        : "=r"(a) : "l"(p));
    return a;
}
__device__ __forceinline__ void cp_async16(uint32_t saddr, const void* g) {
    asm volatile("cp.async.cg.shared.global [%0], [%1], 16;\n" :: "r"(saddr), "l"(g));
}
__device__ __forceinline__ void cp_commit() {
    asm volatile("cp.async.commit_group;\n" ::: "memory");
}
__device__ __forceinline__ void ldsm4(uint32_t& r0, uint32_t& r1, uint32_t& r2,
                                      uint32_t& r3, uint32_t a) {
    asm volatile("ldmatrix.sync.aligned.m8n8.x4.shared.b16 {%0,%1,%2,%3}, [%4];"
                 : "=r"(r0), "=r"(r1), "=r"(r2), "=r"(r3) : "r"(a));
}
__device__ __forceinline__ void mma_f16(float* c, const uint32_t* a, uint32_t b0,
                                        uint32_t b1) {
    asm volatile(
        "mma.sync.aligned.m16n8k16.row.col.f32.f16.f16.f32 "
        "{%0,%1,%2,%3},{%4,%5,%6,%7},{%8,%9},{%0,%1,%2,%3};"
        : "+f"(c[0]), "+f"(c[1]), "+f"(c[2]), "+f"(c[3])
        : "r"(a[0]), "r"(a[1]), "r"(a[2]), "r"(a[3]), "r"(b0), "r"(b1));
}
__device__ __forceinline__ uint32_t pack_h2(float a, float b) {
    uint32_t r;
    asm("cvt.rn.f16x2.f32 %0, %1, %2;" : "=r"(r) : "f"(b), "f"(a));
    return r;
}

// ===========================================================================
// fp32 -> fp16 convert
// ===========================================================================
__global__ __launch_bounds__(256) void cvt16(const float4* __restrict__ src,
                                             uint2* __restrict__ dst) {
    int i = blockIdx.x * 256 + threadIdx.x;
    float4 v = src[i];
    dst[i] = make_uint2(pack_h2(v.x, v.y), pack_h2(v.z, v.w));
}

// ===========================================================================
// softmax over HEAD axis (fp16 S -> fp16 P)
// ===========================================================================
__global__ __launch_bounds__(256) void softmax16() {
    int idx = blockIdx.x * 256 + threadIdx.x;
    int k4 = idx & 511;
    int q = (idx >> 9) & 2047;
    int b = idx >> 20;
    const uint2* Sp = (const uint2*)g_S16;
    uint2* Pp = (uint2*)g_P16;
    size_t base = ((size_t)(b * HH) * SS + q) * 512 + k4;
    size_t hstep = (size_t)SS * 512;

    float4 e[16];
    float4 ds = make_float4(0.f, 0.f, 0.f, 0.f);
#pragma unroll
    for (int h = 0; h < 16; h++) {
        uint2 u = Sp[base + (size_t)h * hstep];
        float2 f0 = __half22float2(*(const __half2*)&u.x);
        float2 f1 = __half22float2(*(const __half2*)&u.y);
        e[h].x = __expf(f0.x * 0.03125f);
        e[h].y = __expf(f0.y * 0.03125f);
        e[h].z = __expf(f1.x * 0.03125f);
        e[h].w = __expf(f1.y * 0.03125f);
        ds.x += e[h].x; ds.y += e[h].y; ds.z += e[h].z; ds.w += e[h].w;
    }
    float4 r;
    r.x = __fdividef(1.f, ds.x);
    r.y = __fdividef(1.f, ds.y);
    r.z = __fdividef(1.f, ds.z);
    r.w = __fdividef(1.f, ds.w);
#pragma unroll
    for (int h = 0; h < 16; h++) {
        uint2 o;
        o.x = pack_h2(e[h].x * r.x, e[h].y * r.y);
        o.y = pack_h2(e[h].z * r.z, e[h].w * r.w);
        Pp[base + (size_t)h * hstep] = o;
    }
}

// ===========================================================================
// Streaming scores kernel: S[z][q][k] = Q[z][q][:] . K[z][k][:], K-dim 64.
// CTA = (q-tile 128, z). Q fragments live in REGISTERS (loaded once);
// K streamed in 128-key double-buffered chunks; S written fp16 per chunk.
// 256 threads, warp grid 4m x 2n (warp tile 32q x 64k per chunk).
// ===========================================================================
#define QK_SMEM (128 * 144 + 2 * 128 * 144)   // Q tile + 2 K buffers = 55296

__global__ __launch_bounds__(256, 2) void qk_stream() {
    extern __shared__ char dsm[];
    uint32_t sbase = smem_u32(dsm);
    const uint32_t kbase = sbase + 128 * 144;

    int z = blockIdx.y;
    const __half* Qg = g_q16 + (size_t)z * SS * DD;
    const __half* Kg = g_k16 + (size_t)z * SS * DD;
    uint32_t* Sp = (uint32_t*)(g_S16 + (size_t)z * SPLANE);

    int tid = threadIdx.x, lane = tid & 31, wid = tid >> 5;
    int wm = wid & 3, wn = wid >> 2;
    int q0 = blockIdx.x * 128;

    // ---- load Q tile 128x64 (pitch 144) ----
#pragma unroll
    for (int it = 0; it < 4; it++) {
        int idx = tid + it * 256;
        int row = idx >> 3, seg = idx & 7;
        cp_async16(sbase + (uint32_t)(row * 144 + seg * 16),
                   Qg + (size_t)(q0 + row) * DD + seg * 8);
    }
    cp_commit();

    auto issueK = [&](int c) {
        uint32_t kb = kbase + (c & 1) * 18432;
        int k0 = c * 128;
#pragma unroll
        for (int it = 0; it < 4; it++) {
            int idx = tid + it * 256;
            int row = idx >> 3, seg = idx & 7;
            cp_async16(kb + (uint32_t)(row * 144 + seg * 16),
                       Kg + (size_t)(k0 + row) * DD + seg * 8);
        }
        cp_commit();
    };

    // wait for Q, move to registers
    asm volatile("cp.async.wait_group 0;\n" ::: "memory");
    __syncthreads();
    uint32_t qf[2][4][4];
    {
        uint32_t qa = sbase + (uint32_t)((wm * 32 + (lane & 15)) * 144 + (lane >> 4) * 16);
#pragma unroll
        for (int mb = 0; mb < 2; mb++)
#pragma unroll
            for (int ks = 0; ks < 4; ks++)
                ldsm4(qf[mb][ks][0], qf[mb][ks][1], qf[mb][ks][2], qf[mb][ks][3],
                      qa + mb * (16 * 144) + ks * 32);
    }

    issueK(0);

    const int NC = SS / 128;   // 16
    int lr = lane >> 2, lc = lane & 3;

    for (int c = 0; c < NC; c++) {
        if (c + 1 < NC) {
            issueK(c + 1);
            asm volatile("cp.async.wait_group 1;\n" ::: "memory");
        } else {
            asm volatile("cp.async.wait_group 0;\n" ::: "memory");
        }
        __syncthreads();

        uint32_t kb = kbase + (c & 1) * 18432;
        uint32_t b_addr = kb + (uint32_t)((wn * 64 + (lane >> 4) * 8 + (lane & 7)) * 144 +
                                          ((lane >> 3) & 1) * 16);

        float acc[2][8][4];
#pragma unroll
        for (int i = 0; i < 2; i++)
#pragma unroll
            for (int j = 0; j < 8; j++)
#pragma unroll
                for (int q = 0; q < 4; q++) acc[i][j][q] = 0.f;

#pragma unroll
        for (int ks = 0; ks < 4; ks++) {
#pragma unroll
            for (int nblk = 0; nblk < 4; nblk++) {
                uint32_t h0, h1, h2, h3;
                ldsm4(h0, h1, h2, h3, b_addr + ks * 32 + nblk * (16 * 144));
#pragma unroll
                for (int mb = 0; mb < 2; mb++) {
                    mma_f16(acc[mb][2 * nblk],     qf[mb][ks], h0, h1);
                    mma_f16(acc[mb][2 * nblk + 1], qf[mb][ks], h2, h3);
                }
            }
        }

        // epilogue: write this chunk's S columns
#pragma unroll
        for (int mb = 0; mb < 2; mb++) {
#pragma unroll
            for (int nb = 0; nb < 8; nb++) {
                int n = c * 128 + wn * 64 + nb * 8 + lc * 2;
                int m = q0 + wm * 32 + mb * 16 + lr;
                float* a4 = acc[mb][nb];
                Sp[((size_t)m * SS + n) >> 1] = pack_h2(a4[0], a4[1]);
                Sp[((size_t)(m + 8) * SS + n) >> 1] = pack_h2(a4[2], a4[3]);
            }
        }
        __syncthreads();
    }
}

// ===========================================================================
// fp16 HMMA NT GEMM (R12 config: 256 thr, 4x2 warp grid) — QKV/out-proj/PV.
// MODE 0: out-proj (bias, fp32 out N=1024)
// MODE 1: QKV (bias; Q,K fp16 [b][h][s][d]; V fp16 transposed [b][h][d][k])
// MODE 3: PV (z=(b,h), NT=64; fp16 ctx out [b][s][e])
// ===========================================================================
template <int MODE, int NT, int K, int KB>
__global__ __launch_bounds__(256, 2) void tgemm16(
    const __half* __restrict__ A0, const __half* __restrict__ W0,
    const float* __restrict__ bias, float* __restrict__ Cout,
    int strideA, int strideW) {
    extern __shared__ char dsm[];
    uint32_t sbase = smem_u32(dsm);
    constexpr int PITCH = KB * 2 + 16;
    constexpr int TILE_A = 128 * PITCH;
    constexpr int TILE_W = NT * PITCH;
    constexpr int BUF = TILE_A + TILE_W;
    constexpr int NP = NT / 32;
    constexpr int SEG = KB / 8;
    constexpr int NKS = KB / 16;

    int z = blockIdx.z;
    const __half* A = A0 + (size_t)z * strideA;
    const __half* W = W0 + (size_t)z * strideW;

    int tid = threadIdx.x, lane = tid & 31, wid = tid >> 5;
    int wm = wid & 3, wn = wid >> 2;
    int m0 = blockIdx.y * 128, n0 = blockIdx.x * NT;

    float acc[2][2 * NP][4];
#pragma unroll
    for (int i = 0; i < 2; i++)
#pragma unroll
        for (int j = 0; j < 2 * NP; j++)
#pragma unroll
            for (int q = 0; q < 4; q++) acc[i][j][q] = 0.f;

    const int NC = K / KB;

    auto issue = [&](int c) {
        uint32_t sb = sbase + (c & 1) * BUF;
        int gc = c * KB;
#pragma unroll
        for (int it = 0; it < 128 * SEG / 256; it++) {
            int idx = tid + it * 256;
            int row = idx / SEG, seg = idx % SEG;
            cp_async16(sb + (uint32_t)(row * PITCH + seg * 16),
                       A + (size_t)(m0 + row) * K + gc + seg * 8);
        }
#pragma unroll
        for (int it = 0; it < NT * SEG / 256; it++) {
            int idx = tid + it * 256;
            int row = idx / SEG, seg = idx % SEG;
            cp_async16(sb + (uint32_t)(TILE_A + row * PITCH + seg * 16),
                       W + (size_t)(n0 + row) * K + gc + seg * 8);
        }
        cp_commit();
    };

    issue(0);

    for (int c = 0; c < NC; c++) {
        if (c + 1 < NC) {
            issue(c + 1);
            asm volatile("cp.async.wait_group 1;\n" ::: "memory");
        } else {
            asm volatile("cp.async.wait_group 0;\n" ::: "memory");
        }
        __syncthreads();

        uint32_t sb = sbase + (c & 1) * BUF;
        uint32_t a_addr = sb + (uint32_t)((wm * 32 + (lane & 15)) * PITCH + (lane >> 4) * 16);
        uint32_t b_addr = sb + TILE_A +
                          (uint32_t)((wn * (NT / 2) + (lane >> 4) * 8 + (lane & 7)) * PITCH +
                                     ((lane >> 3) & 1) * 16);

#pragma unroll
        for (int ks = 0; ks < NKS; ks++) {
            uint32_t ah[2][4];
#pragma unroll
            for (int mb = 0; mb < 2; mb++) {
                uint32_t ao = a_addr + ks * 32 + mb * (16 * PITCH);
                ldsm4(ah[mb][0], ah[mb][1], ah[mb][2], ah[mb][3], ao);
            }
#pragma unroll
            for (int np = 0; np < NP; np++) {
                uint32_t bo = b_addr + ks * 32 + np * (16 * PITCH);
                uint32_t h0, h1, h2, h3;
                ldsm4(h0, h1, h2, h3, bo);
#pragma unroll
                for (int mb = 0; mb < 2; mb++) {
                    mma_f16(acc[mb][2 * np],     ah[mb], h0, h1);
                    mma_f16(acc[mb][2 * np + 1], ah[mb], h2, h3);
                }
            }
        }
        __syncthreads();
    }

    int lr = lane >> 2, lc = lane & 3;
#pragma unroll
    for (int mb = 0; mb < 2; mb++) {
#pragma unroll
        for (int nb = 0; nb < 2 * NP; nb++) {
            int n = n0 + wn * (NT / 2) + nb * 8 + lc * 2;
            int m_lo = m0 + wm * 32 + mb * 16 + lr;
            float* a4 = acc[mb][nb];
            if constexpr (MODE == 0) {
                float2 bv = *(const float2*)(bias + n);
                *(float2*)(Cout + (size_t)m_lo * 1024 + n) =
                    make_float2(a4[0] + bv.x, a4[1] + bv.y);
                *(float2*)(Cout + (size_t)(m_lo + 8) * 1024 + n) =
                    make_float2(a4[2] + bv.x, a4[3] + bv.y);
            } else if constexpr (MODE == 1) {
                float2 bv = *(const float2*)(bias + n);
                int which = n >> 10;
                int hh = (n & 1023) >> 6;
                int d = n & 63;
#pragma unroll
                for (int half_ = 0; half_ < 2; half_++) {
                    int m = m_lo + half_ * 8;
                    int b_ = m >> 11;
                    int s = m & 2047;
                    float v0 = a4[2 * half_] + bv.x;
                    float v1 = a4[2 * half_ + 1] + bv.y;
                    if (which == 2) {
                        size_t tb = ((size_t)(b_ * HH + hh) * DD + d) * SS + s;
                        g_vt16[tb] = __float2half_rn(v0);
                        g_vt16[tb + SS] = __float2half_rn(v1);
                    } else {
                        size_t idx = (((size_t)b_ * HH + hh) * SS + s) * DD + d;
                        uint32_t* ph = which ? (uint32_t*)g_k16 : (uint32_t*)g_q16;
                        ph[idx >> 1] = pack_h2(v0, v1);
                    }
                }
            } else {
                int b_ = z >> 4, h_ = z & 15;
                uint32_t* ch = (uint32_t*)g_ctx16;
                size_t i0 = ((size_t)(b_ * SS + m_lo) * EE + h_ * DD + n) >> 1;
                ch[i0] = pack_h2(a4[0], a4[1]);
                ch[i0 + 4 * EE] = pack_h2(a4[2], a4[3]);
            }
        }
    }
}

// ===========================================================================
extern "C" void kernel_launch(void* const* d_in, const int* in_sizes, int n_in,
                              void* d_out, int out_size) {
    const float* x     = (const float*)d_in[0];
    const float* w_qkv = (const float*)d_in[1];
    const float* b_qkv = (const float*)d_in[2];
    const float* w_out = (const float*)d_in[3];
    const float* b_out = (const float*)d_in[4];
    float* out = (float*)d_out;

    void *p_x, *p_wq, *p_wo, *p_P, *p_vt, *p_ctx;
    cudaGetSymbolAddress(&p_x, g_x16);
    cudaGetSymbolAddress(&p_wq, g_wq16);
    cudaGetSymbolAddress(&p_wo, g_wo16);
    cudaGetSymbolAddress(&p_P, g_P16);
    cudaGetSymbolAddress(&p_vt, g_vt16);
    cudaGetSymbolAddress(&p_ctx, g_ctx16);

    const int SM_QKV = 2 * (128 * 144 + 128 * 144);   // 73728 (KB=64, NT=128)
    const int SM_PV  = 2 * (128 * 144 + 64 * 144);    // 55296 (KB=64, NT=64)
    cudaFuncSetAttribute(tgemm16<1, 128, 1024, 64>, cudaFuncAttributeMaxDynamicSharedMemorySize, SM_QKV);
    cudaFuncSetAttribute(tgemm16<0, 128, 1024, 64>, cudaFuncAttributeMaxDynamicSharedMemorySize, SM_QKV);
    cudaFuncSetAttribute(tgemm16<3, 64, 2048, 64>,  cudaFuncAttributeMaxDynamicSharedMemorySize, SM_PV);
    cudaFuncSetAttribute(qk_stream, cudaFuncAttributeMaxDynamicSharedMemorySize, QK_SMEM);

    // 1) fp32 -> fp16 converts
    cvt16<<<4096, 256>>>((const float4*)x, (uint2*)p_x);
    cvt16<<<3072, 256>>>((const float4*)w_qkv, (uint2*)p_wq);
    cvt16<<<1024, 256>>>((const float4*)w_out, (uint2*)p_wo);

    // 2) QKV projection -> Q,K fp16 + V fp16 transposed
    tgemm16<1, 128, 1024, 64><<<dim3(24, 32, 1), 256, SM_QKV>>>(
        (const __half*)p_x, (const __half*)p_wq, b_qkv, nullptr, 0, 0);

    // 3) streaming scores S = Q K^T -> fp16 (Q in registers)
    qk_stream<<<dim3(16, 32), 256, QK_SMEM>>>();

    // 4) softmax over heads -> P fp16
    softmax16<<<8192, 256>>>();

    // 5) ctx = P V -> fp16 [b][s][e]
    tgemm16<3, 64, 2048, 64><<<dim3(1, 16, 32), 256, SM_PV>>>(
        (const __half*)p_P, (const __half*)p_vt, nullptr, nullptr,
        (int)SPLANE, DD * SS);

    // 6) out-projection -> fp32 out
    tgemm16<0, 128, 1024, 64><<<dim3(8, 32, 1), 256, SM_QKV>>>(
        (const __half*)p_ctx, (const __half*)p_wo, b_out, out, 0, 0);
}

// round 17
// speedup vs baseline: 1.4304x; 1.0209x over previous
#include <cuda_runtime.h>
#include <cuda_fp16.h>
#include <cstdint>

#define BB 2
#define SS 2048
#define EE 1024
#define HH 16
#define DD 64
#define QKPLANE (BB * HH * SS * DD)
#define SPLANE ((size_t)SS * SS)

__device__ __half g_x16[4096 * 1024];
__device__ __half g_wq16[3072 * 1024];
__device__ __half g_wo16[1024 * 1024];
__device__ __half g_q16[QKPLANE];                 // [b][h][s][d]
__device__ __half g_k16[QKPLANE];
__device__ __half g_vt16[QKPLANE];                // [b][h][d][k]
__device__ __half g_S16[(size_t)BB * HH * SS * SS];   // e = exp(S/32)
__device__ __half g_P16[(size_t)BB * HH * SS * SS];
__device__ __half g_ctx16[BB * SS * EE];          // [b][s][h*64+d]

// ===========================================================================
// helpers
// ===========================================================================
__device__ __forceinline__ uint32_t smem_u32(const void* p) {
    uint32_t a;
    asm("{ .reg .u64 t; cvta.to.shared.u64 t, %1; cvt.u32.u64 %0, t; }"
        : "=r"(a) : "l"(p));
    return a;
}
__device__ __forceinline__ void cp_async16(uint32_t saddr, const void* g) {
    asm volatile("cp.async.cg.shared.global [%0], [%1], 16;\n" :: "r"(saddr), "l"(g));
}
__device__ __forceinline__ void cp_commit() {
    asm volatile("cp.async.commit_group;\n" ::: "memory");
}
__device__ __forceinline__ void ldsm4(uint32_t& r0, uint32_t& r1, uint32_t& r2,
                                      uint32_t& r3, uint32_t a) {
    asm volatile("ldmatrix.sync.aligned.m8n8.x4.shared.b16 {%0,%1,%2,%3}, [%4];"
                 : "=r"(r0), "=r"(r1), "=r"(r2), "=r"(r3) : "r"(a));
}
__device__ __forceinline__ void mma_f16(float* c, const uint32_t* a, uint32_t b0,
                                        uint32_t b1) {
    asm volatile(
        "mma.sync.aligned.m16n8k16.row.col.f32.f16.f16.f32 "
        "{%0,%1,%2,%3},{%4,%5,%6,%7},{%8,%9},{%0,%1,%2,%3};"
        : "+f"(c[0]), "+f"(c[1]), "+f"(c[2]), "+f"(c[3])
        : "r"(a[0]), "r"(a[1]), "r"(a[2]), "r"(a[3]), "r"(b0), "r"(b1));
}
__device__ __forceinline__ uint32_t pack_h2(float a, float b) {
    uint32_t r;
    asm("cvt.rn.f16x2.f32 %0, %1, %2;" : "=r"(r) : "f"(b), "f"(a));
    return r;
}

// ===========================================================================
// fused fp32 -> fp16 convert for x, w_qkv, w_out (one launch)
// ===========================================================================
#define NX 1048576
#define NWQ 786432
#define NWO 262144
__global__ __launch_bounds__(256) void cvt16_all(const float4* __restrict__ x,
                                                 const float4* __restrict__ wq,
                                                 const float4* __restrict__ wo) {
    int i = blockIdx.x * 256 + threadIdx.x;
    const float4* src;
    uint2* dst;
    int j;
    if (i < NX) {
        src = x; dst = (uint2*)g_x16; j = i;
    } else if (i < NX + NWQ) {
        src = wq; dst = (uint2*)g_wq16; j = i - NX;
    } else {
        src = wo; dst = (uint2*)g_wo16; j = i - NX - NWQ;
    }
    float4 v = src[j];
    dst[j] = make_uint2(pack_h2(v.x, v.y), pack_h2(v.z, v.w));
}

// ===========================================================================
// normalize over HEAD axis: P = e / sum_h e   (e precomputed by qk_stream)
// ===========================================================================
__global__ __launch_bounds__(256) void softmax16() {
    int idx = blockIdx.x * 256 + threadIdx.x;
    int k4 = idx & 511;
    int q = (idx >> 9) & 2047;
    int b = idx >> 20;
    const uint2* Sp = (const uint2*)g_S16;
    uint2* Pp = (uint2*)g_P16;
    size_t base = ((size_t)(b * HH) * SS + q) * 512 + k4;
    size_t hstep = (size_t)SS * 512;

    float4 e[16];
    float4 ds = make_float4(0.f, 0.f, 0.f, 0.f);
#pragma unroll
    for (int h = 0; h < 16; h++) {
        uint2 u = Sp[base + (size_t)h * hstep];
        float2 f0 = __half22float2(*(const __half2*)&u.x);
        float2 f1 = __half22float2(*(const __half2*)&u.y);
        e[h] = make_float4(f0.x, f0.y, f1.x, f1.y);
        ds.x += e[h].x; ds.y += e[h].y; ds.z += e[h].z; ds.w += e[h].w;
    }
    float4 r;
    r.x = __fdividef(1.f, ds.x);
    r.y = __fdividef(1.f, ds.y);
    r.z = __fdividef(1.f, ds.z);
    r.w = __fdividef(1.f, ds.w);
#pragma unroll
    for (int h = 0; h < 16; h++) {
        uint2 o;
        o.x = pack_h2(e[h].x * r.x, e[h].y * r.y);
        o.y = pack_h2(e[h].z * r.z, e[h].w * r.w);
        Pp[base + (size_t)h * hstep] = o;
    }
}

// ===========================================================================
// Streaming scores kernel: writes e = exp(QK^T / 32) fp16.
// CTA = (q-tile 128, z). Q fragments in registers; K double-buffered.
// ===========================================================================
#define QK_SMEM (128 * 144 + 2 * 128 * 144)   // 55296

__global__ __launch_bounds__(256, 2) void qk_stream() {
    extern __shared__ char dsm[];
    uint32_t sbase = smem_u32(dsm);
    const uint32_t kbase = sbase + 128 * 144;

    int z = blockIdx.y;
    const __half* Qg = g_q16 + (size_t)z * SS * DD;
    const __half* Kg = g_k16 + (size_t)z * SS * DD;
    uint32_t* Sp = (uint32_t*)(g_S16 + (size_t)z * SPLANE);

    int tid = threadIdx.x, lane = tid & 31, wid = tid >> 5;
    int wm = wid & 3, wn = wid >> 2;
    int q0 = blockIdx.x * 128;

#pragma unroll
    for (int it = 0; it < 4; it++) {
        int idx = tid + it * 256;
        int row = idx >> 3, seg = idx & 7;
        cp_async16(sbase + (uint32_t)(row * 144 + seg * 16),
                   Qg + (size_t)(q0 + row) * DD + seg * 8);
    }
    cp_commit();

    auto issueK = [&](int c) {
        uint32_t kb = kbase + (c & 1) * 18432;
        int k0 = c * 128;
#pragma unroll
        for (int it = 0; it < 4; it++) {
            int idx = tid + it * 256;
            int row = idx >> 3, seg = idx & 7;
            cp_async16(kb + (uint32_t)(row * 144 + seg * 16),
                       Kg + (size_t)(k0 + row) * DD + seg * 8);
        }
        cp_commit();
    };

    asm volatile("cp.async.wait_group 0;\n" ::: "memory");
    __syncthreads();
    uint32_t qf[2][4][4];
    {
        uint32_t qa = sbase + (uint32_t)((wm * 32 + (lane & 15)) * 144 + (lane >> 4) * 16);
#pragma unroll
        for (int mb = 0; mb < 2; mb++)
#pragma unroll
            for (int ks = 0; ks < 4; ks++)
                ldsm4(qf[mb][ks][0], qf[mb][ks][1], qf[mb][ks][2], qf[mb][ks][3],
                      qa + mb * (16 * 144) + ks * 32);
    }

    issueK(0);

    const int NC = SS / 128;
    int lr = lane >> 2, lc = lane & 3;

    for (int c = 0; c < NC; c++) {
        if (c + 1 < NC) {
            issueK(c + 1);
            asm volatile("cp.async.wait_group 1;\n" ::: "memory");
        } else {
            asm volatile("cp.async.wait_group 0;\n" ::: "memory");
        }
        __syncthreads();

        uint32_t kb = kbase + (c & 1) * 18432;
        uint32_t b_addr = kb + (uint32_t)((wn * 64 + (lane >> 4) * 8 + (lane & 7)) * 144 +
                                          ((lane >> 3) & 1) * 16);

        float acc[2][8][4];
#pragma unroll
        for (int i = 0; i < 2; i++)
#pragma unroll
            for (int j = 0; j < 8; j++)
#pragma unroll
                for (int q = 0; q < 4; q++) acc[i][j][q] = 0.f;

#pragma unroll
        for (int ks = 0; ks < 4; ks++) {
#pragma unroll
            for (int nblk = 0; nblk < 4; nblk++) {
                uint32_t h0, h1, h2, h3;
                ldsm4(h0, h1, h2, h3, b_addr + ks * 32 + nblk * (16 * 144));
#pragma unroll
                for (int mb = 0; mb < 2; mb++) {
                    mma_f16(acc[mb][2 * nblk],     qf[mb][ks], h0, h1);
                    mma_f16(acc[mb][2 * nblk + 1], qf[mb][ks], h2, h3);
                }
            }
        }

        // epilogue: e = exp(S/32) -> fp16
#pragma unroll
        for (int mb = 0; mb < 2; mb++) {
#pragma unroll
            for (int nb = 0; nb < 8; nb++) {
                int n = c * 128 + wn * 64 + nb * 8 + lc * 2;
                int m = q0 + wm * 32 + mb * 16 + lr;
                float* a4 = acc[mb][nb];
                Sp[((size_t)m * SS + n) >> 1] =
                    pack_h2(__expf(a4[0] * 0.03125f), __expf(a4[1] * 0.03125f));
                Sp[((size_t)(m + 8) * SS + n) >> 1] =
                    pack_h2(__expf(a4[2] * 0.03125f), __expf(a4[3] * 0.03125f));
            }
        }
        __syncthreads();
    }
}

// ===========================================================================
// fp16 HMMA NT GEMM (256 thr, 4x2 warp grid), chunk depth KB.
// MODE 0: out-proj (bias, fp32 out N=1024)
// MODE 1: QKV (bias; Q,K fp16; V fp16 transposed)
// MODE 3: PV (z=(b,h), NT=64; fp16 ctx out [b][s][e])
// ===========================================================================
template <int MODE, int NT, int K, int KB>
__global__ __launch_bounds__(256, 2) void tgemm16(
    const __half* __restrict__ A0, const __half* __restrict__ W0,
    const float* __restrict__ bias, float* __restrict__ Cout,
    int strideA, int strideW) {
    extern __shared__ char dsm[];
    uint32_t sbase = smem_u32(dsm);
    constexpr int PITCH = KB * 2 + 16;
    constexpr int TILE_A = 128 * PITCH;
    constexpr int TILE_W = NT * PITCH;
    constexpr int BUF = TILE_A + TILE_W;
    constexpr int NP = NT / 32;
    constexpr int SEG = KB / 8;
    constexpr int NKS = KB / 16;

    int z = blockIdx.z;
    const __half* A = A0 + (size_t)z * strideA;
    const __half* W = W0 + (size_t)z * strideW;

    int tid = threadIdx.x, lane = tid & 31, wid = tid >> 5;
    int wm = wid & 3, wn = wid >> 2;
    int m0 = blockIdx.y * 128, n0 = blockIdx.x * NT;

    float acc[2][2 * NP][4];
#pragma unroll
    for (int i = 0; i < 2; i++)
#pragma unroll
        for (int j = 0; j < 2 * NP; j++)
#pragma unroll
            for (int q = 0; q < 4; q++) acc[i][j][q] = 0.f;

    const int NC = K / KB;

    auto issue = [&](int c) {
        uint32_t sb = sbase + (c & 1) * BUF;
        int gc = c * KB;
#pragma unroll
        for (int it = 0; it < 128 * SEG / 256; it++) {
            int idx = tid + it * 256;
            int row = idx / SEG, seg = idx % SEG;
            cp_async16(sb + (uint32_t)(row * PITCH + seg * 16),
                       A + (size_t)(m0 + row) * K + gc + seg * 8);
        }
#pragma unroll
        for (int it = 0; it < NT * SEG / 256; it++) {
            int idx = tid + it * 256;
            int row = idx / SEG, seg = idx % SEG;
            cp_async16(sb + (uint32_t)(TILE_A + row * PITCH + seg * 16),
                       W + (size_t)(n0 + row) * K + gc + seg * 8);
        }
        cp_commit();
    };

    issue(0);

    for (int c = 0; c < NC; c++) {
        if (c + 1 < NC) {
            issue(c + 1);
            asm volatile("cp.async.wait_group 1;\n" ::: "memory");
        } else {
            asm volatile("cp.async.wait_group 0;\n" ::: "memory");
        }
        __syncthreads();

        uint32_t sb = sbase + (c & 1) * BUF;
        uint32_t a_addr = sb + (uint32_t)((wm * 32 + (lane & 15)) * PITCH + (lane >> 4) * 16);
        uint32_t b_addr = sb + TILE_A +
                          (uint32_t)((wn * (NT / 2) + (lane >> 4) * 8 + (lane & 7)) * PITCH +
                                     ((lane >> 3) & 1) * 16);

#pragma unroll
        for (int ks = 0; ks < NKS; ks++) {
            uint32_t ah[2][4];
#pragma unroll
            for (int mb = 0; mb < 2; mb++) {
                uint32_t ao = a_addr + ks * 32 + mb * (16 * PITCH);
                ldsm4(ah[mb][0], ah[mb][1], ah[mb][2], ah[mb][3], ao);
            }
#pragma unroll
            for (int np = 0; np < NP; np++) {
                uint32_t bo = b_addr + ks * 32 + np * (16 * PITCH);
                uint32_t h0, h1, h2, h3;
                ldsm4(h0, h1, h2, h3, bo);
#pragma unroll
                for (int mb = 0; mb < 2; mb++) {
                    mma_f16(acc[mb][2 * np],     ah[mb], h0, h1);
                    mma_f16(acc[mb][2 * np + 1], ah[mb], h2, h3);
                }
            }
        }
        __syncthreads();
    }

    int lr = lane >> 2, lc = lane & 3;
#pragma unroll
    for (int mb = 0; mb < 2; mb++) {
#pragma unroll
        for (int nb = 0; nb < 2 * NP; nb++) {
            int n = n0 + wn * (NT / 2) + nb * 8 + lc * 2;
            int m_lo = m0 + wm * 32 + mb * 16 + lr;
            float* a4 = acc[mb][nb];
            if constexpr (MODE == 0) {
                float2 bv = *(const float2*)(bias + n);
                *(float2*)(Cout + (size_t)m_lo * 1024 + n) =
                    make_float2(a4[0] + bv.x, a4[1] + bv.y);
                *(float2*)(Cout + (size_t)(m_lo + 8) * 1024 + n) =
                    make_float2(a4[2] + bv.x, a4[3] + bv.y);
            } else if constexpr (MODE == 1) {
                float2 bv = *(const float2*)(bias + n);
                int which = n >> 10;
                int hh = (n & 1023) >> 6;
                int d = n & 63;
#pragma unroll
                for (int half_ = 0; half_ < 2; half_++) {
                    int m = m_lo + half_ * 8;
                    int b_ = m >> 11;
                    int s = m & 2047;
                    float v0 = a4[2 * half_] + bv.x;
                    float v1 = a4[2 * half_ + 1] + bv.y;
                    if (which == 2) {
                        size_t tb = ((size_t)(b_ * HH + hh) * DD + d) * SS + s;
                        g_vt16[tb] = __float2half_rn(v0);
                        g_vt16[tb + SS] = __float2half_rn(v1);
                    } else {
                        size_t idx = (((size_t)b_ * HH + hh) * SS + s) * DD + d;
                        uint32_t* ph = which ? (uint32_t*)g_k16 : (uint32_t*)g_q16;
                        ph[idx >> 1] = pack_h2(v0, v1);
                    }
                }
            } else {
                int b_ = z >> 4, h_ = z & 15;
                uint32_t* ch = (uint32_t*)g_ctx16;
                size_t i0 = ((size_t)(b_ * SS + m_lo) * EE + h_ * DD + n) >> 1;
                ch[i0] = pack_h2(a4[0], a4[1]);
                ch[i0 + 4 * EE] = pack_h2(a4[2], a4[3]);
            }
        }
    }
}

// ===========================================================================
extern "C" void kernel_launch(void* const* d_in, const int* in_sizes, int n_in,
                              void* d_out, int out_size) {
    const float* x     = (const float*)d_in[0];
    const float* w_qkv = (const float*)d_in[1];
    const float* b_qkv = (const float*)d_in[2];
    const float* w_out = (const float*)d_in[3];
    const float* b_out = (const float*)d_in[4];
    float* out = (float*)d_out;

    void *p_x, *p_wq, *p_wo, *p_P, *p_vt, *p_ctx;
    cudaGetSymbolAddress(&p_x, g_x16);
    cudaGetSymbolAddress(&p_wq, g_wq16);
    cudaGetSymbolAddress(&p_wo, g_wo16);
    cudaGetSymbolAddress(&p_P, g_P16);
    cudaGetSymbolAddress(&p_vt, g_vt16);
    cudaGetSymbolAddress(&p_ctx, g_ctx16);

    const int SM_QKV = 2 * (128 * 144 + 128 * 144);    // 73728 (KB=64, NT=128)
    const int SM_PV  = 2 * (128 * 272 + 64 * 272);     // 104448 (KB=128, NT=64)
    cudaFuncSetAttribute(tgemm16<1, 128, 1024, 64>, cudaFuncAttributeMaxDynamicSharedMemorySize, SM_QKV);
    cudaFuncSetAttribute(tgemm16<0, 128, 1024, 64>, cudaFuncAttributeMaxDynamicSharedMemorySize, SM_QKV);
    cudaFuncSetAttribute(tgemm16<3, 64, 2048, 128>, cudaFuncAttributeMaxDynamicSharedMemorySize, SM_PV);
    cudaFuncSetAttribute(qk_stream, cudaFuncAttributeMaxDynamicSharedMemorySize, QK_SMEM);

    // 1) fused fp32 -> fp16 converts (one launch)
    cvt16_all<<<8192, 256>>>((const float4*)x, (const float4*)w_qkv,
                             (const float4*)w_out);

    // 2) QKV projection -> Q,K fp16 + V fp16 transposed
    tgemm16<1, 128, 1024, 64><<<dim3(24, 32, 1), 256, SM_QKV>>>(
        (const __half*)p_x, (const __half*)p_wq, b_qkv, nullptr, 0, 0);

    // 3) streaming scores -> e = exp(S/32) fp16
    qk_stream<<<dim3(16, 32), 256, QK_SMEM>>>();

    // 4) normalize over heads -> P fp16
    softmax16<<<8192, 256>>>();

    // 5) ctx = P V -> fp16 [b][s][e]  (KB=128)
    tgemm16<3, 64, 2048, 128><<<dim3(1, 16, 32), 256, SM_PV>>>(
        (const __half*)p_P, (const __half*)p_vt, nullptr, nullptr,
        (int)SPLANE, DD * SS);

    // 6) out-projection -> fp32 out
    tgemm16<0, 128, 1024, 64><<<dim3(8, 32, 1), 256, SM_QKV>>>(
        (const __half*)p_ctx, (const __half*)p_wo, b_out, out, 0, 0);
}